// round 9
// baseline (speedup 1.0000x reference)
#include <cuda_runtime.h>

// out[n][c] = in[n][c] + glob[batch[n]][c]
// N = 1,000,000, C = 128, B = 8, fp32.  ~1.03 GB streamed.
//
// R9: identical to the proven R6/R8 config (flat grid, 512-thread blocks,
// ILP=4 front-batched LDG.128, unguarded fast path, 32-bit indexing) with
// ONE change: default cache policy on the read stream (ld.global.nc),
// evict-first (.cs) kept only on the store stream.

static constexpr int C_VEC   = 128 / 4;  // 32 float4 per row
static constexpr int UNROLL  = 4;
static constexpr int THREADS = 512;

template <bool GUARD>
__global__ __launch_bounds__(THREADS)
void sparse_global_broadcast_kernel(const float4* __restrict__ in,
                                    const float4* __restrict__ glob,
                                    const int*    __restrict__ bidx,
                                    float4*       __restrict__ out,
                                    unsigned n_vec) {
    unsigned base = blockIdx.x * (THREADS * UNROLL) + threadIdx.x;

    float4 a[UNROLL];
    int    b[UNROLL];

    // Front-batch all independent loads: 4x LDG.128 + 4x LDG.32 (bidx).
    #pragma unroll
    for (int u = 0; u < UNROLL; u++) {
        unsigned i = base + u * THREADS;
        if (!GUARD || i < n_vec) {
            a[u] = __ldg(&in[i]);             // default policy read stream
            b[u] = __ldg(&bidx[i >> 5]);      // warp-uniform row index, cached
        }
    }

    #pragma unroll
    for (int u = 0; u < UNROLL; u++) {
        unsigned i = base + u * THREADS;
        if (!GUARD || i < n_vec) {
            unsigned lane = i & 31;
            float4 g = __ldg(&glob[(unsigned)b[u] * C_VEC + lane]);  // 4 KB, L1-hit
            float4 r;
            r.x = a[u].x + g.x;
            r.y = a[u].y + g.y;
            r.z = a[u].z + g.z;
            r.w = a[u].w + g.w;
            __stcs(&out[i], r);               // evict-first store stream
        }
    }
}

extern "C" void kernel_launch(void* const* d_in, const int* in_sizes, int n_in,
                              void* d_out, int out_size) {
    const float4* in   = (const float4*)d_in[0];   // input_features        [N, C]
    const float4* glob = (const float4*)d_in[1];   // input_features_global [B, C]
    const int*    bidx = (const int*)d_in[2];      // batch_indices         [N]

    float4* out = (float4*)d_out;

    unsigned n_vec = (unsigned)((long long)in_sizes[0] / 4);   // N*C/4 = 32M
    unsigned per_block = THREADS * UNROLL;                      // 2048
    unsigned blocks = (n_vec + per_block - 1) / per_block;      // 15625

    if (n_vec % per_block == 0) {
        sparse_global_broadcast_kernel<false><<<blocks, THREADS>>>(in, glob, bidx, out, n_vec);
    } else {
        sparse_global_broadcast_kernel<true><<<blocks, THREADS>>>(in, glob, bidx, out, n_vec);
    }
}

// round 10
// speedup vs baseline: 1.0201x; 1.0201x over previous
#include <cuda_runtime.h>

// out[n][c] = in[n][c] + glob[batch[n]][c]
// N = 1,000,000, C = 128, B = 8, fp32.  ~1.03 GB streamed.
//
// FINAL (R6/R8 config, best measured: 149.5 us bench / 144.2 us ncu / 85.1% DRAM):
// flat grid, 512-thread blocks, ILP=4 front-batched LDG.128 with evict-first
// hints on BOTH streams, unguarded fast path, 32-bit indexing.
// Eight structurally different variants (ILP 4/8, blocks 256/512, float4/vec8,
// flat/persistent, cache-policy sweeps) all converge to ~144 us kernel time:
// the HBM mixed read/write streaming ceiling (~6.75 TB/s) is reached.

static constexpr int C_VEC   = 128 / 4;  // 32 float4 per row
static constexpr int UNROLL  = 4;
static constexpr int THREADS = 512;

template <bool GUARD>
__global__ __launch_bounds__(THREADS)
void sparse_global_broadcast_kernel(const float4* __restrict__ in,
                                    const float4* __restrict__ glob,
                                    const int*    __restrict__ bidx,
                                    float4*       __restrict__ out,
                                    unsigned n_vec) {
    unsigned base = blockIdx.x * (THREADS * UNROLL) + threadIdx.x;

    float4 a[UNROLL];
    int    b[UNROLL];

    // Front-batch all independent loads: 4x LDG.128 (stream) + 4x LDG.32 (bidx).
    #pragma unroll
    for (int u = 0; u < UNROLL; u++) {
        unsigned i = base + u * THREADS;
        if (!GUARD || i < n_vec) {
            a[u] = __ldcs(&in[i]);            // evict-first streaming load
            b[u] = __ldg(&bidx[i >> 5]);      // warp-uniform row index, cached
        }
    }

    #pragma unroll
    for (int u = 0; u < UNROLL; u++) {
        unsigned i = base + u * THREADS;
        if (!GUARD || i < n_vec) {
            unsigned lane = i & 31;
            float4 g = __ldg(&glob[(unsigned)b[u] * C_VEC + lane]);  // 4 KB, L1-hit
            float4 r;
            r.x = a[u].x + g.x;
            r.y = a[u].y + g.y;
            r.z = a[u].z + g.z;
            r.w = a[u].w + g.w;
            __stcs(&out[i], r);               // streaming store
        }
    }
}

extern "C" void kernel_launch(void* const* d_in, const int* in_sizes, int n_in,
                              void* d_out, int out_size) {
    const float4* in   = (const float4*)d_in[0];   // input_features        [N, C]
    const float4* glob = (const float4*)d_in[1];   // input_features_global [B, C]
    const int*    bidx = (const int*)d_in[2];      // batch_indices         [N]

    float4* out = (float4*)d_out;

    unsigned n_vec = (unsigned)((long long)in_sizes[0] / 4);   // N*C/4 = 32M
    unsigned per_block = THREADS * UNROLL;                      // 2048
    unsigned blocks = (n_vec + per_block - 1) / per_block;      // 15625

    if (n_vec % per_block == 0) {
        sparse_global_broadcast_kernel<false><<<blocks, THREADS>>>(in, glob, bidx, out, n_vec);
    } else {
        sparse_global_broadcast_kernel<true><<<blocks, THREADS>>>(in, glob, bidx, out, n_vec);
    }
}

// round 11
// speedup vs baseline: 1.0214x; 1.0013x over previous
#include <cuda_runtime.h>

// out[n][c] = in[n][c] + glob[batch[n]][c]
// N = 1,000,000, C = 128, B = 8, fp32.  ~1.03 GB streamed, ~7.1 TB/s at pins.
//
// R11: R8 config (flat grid, 512-thr blocks, ILP=4 LDG.128 .cs, unguarded path)
// + sorted-batch block-uniform shortcut: each block reads bidx at its first and
// last row only; if equal (all but ~7 of 15625 blocks), skip the per-element
// bidx loads entirely. Cuts bidx DRAM traffic ~4MB -> ~1MB and removes 4
// LDG.32/thread from the L1tex queue. Boundary blocks take the per-u fallback.

static constexpr int C_VEC   = 128 / 4;  // 32 float4 per row
static constexpr int UNROLL  = 4;
static constexpr int THREADS = 512;

template <bool GUARD>
__global__ __launch_bounds__(THREADS)
void sparse_global_broadcast_kernel(const float4* __restrict__ in,
                                    const float4* __restrict__ glob,
                                    const int*    __restrict__ bidx,
                                    float4*       __restrict__ out,
                                    unsigned n_vec) {
    const unsigned chunk = THREADS * UNROLL;               // 2048 float4 = 64 rows
    unsigned blockStart = blockIdx.x * chunk;
    unsigned base = blockStart + threadIdx.x;

    // Sorted batch_indices: if first and last row of this block agree, the
    // whole block is one batch. Block-uniform -> no divergence.
    unsigned rowFirst = blockStart >> 5;
    unsigned rowLast  = (blockStart + chunk - 1) >> 5;
    if (GUARD) {
        unsigned rowMax = (n_vec - 1) >> 5;
        if (rowLast > rowMax) rowLast = rowMax;
    }
    int b_first = __ldg(&bidx[rowFirst]);
    int b_last  = __ldg(&bidx[rowLast]);
    bool uniform = (b_first == b_last);

    float4 a[UNROLL];
    int    b[UNROLL];

    // Front-batch independent loads: 4x LDG.128 (stream); bidx loads predicated
    // off in the (overwhelmingly common) uniform case.
    #pragma unroll
    for (int u = 0; u < UNROLL; u++) {
        unsigned i = base + u * THREADS;
        if (!GUARD || i < n_vec) {
            a[u] = __ldcs(&in[i]);                        // evict-first stream
            b[u] = uniform ? b_first : __ldg(&bidx[i >> 5]);
        }
    }

    #pragma unroll
    for (int u = 0; u < UNROLL; u++) {
        unsigned i = base + u * THREADS;
        if (!GUARD || i < n_vec) {
            unsigned lane = i & 31;
            float4 g = __ldg(&glob[(unsigned)b[u] * C_VEC + lane]);  // 4 KB, L1-hit
            float4 r;
            r.x = a[u].x + g.x;
            r.y = a[u].y + g.y;
            r.z = a[u].z + g.z;
            r.w = a[u].w + g.w;
            __stcs(&out[i], r);                           // streaming store
        }
    }
}

extern "C" void kernel_launch(void* const* d_in, const int* in_sizes, int n_in,
                              void* d_out, int out_size) {
    const float4* in   = (const float4*)d_in[0];   // input_features        [N, C]
    const float4* glob = (const float4*)d_in[1];   // input_features_global [B, C]
    const int*    bidx = (const int*)d_in[2];      // batch_indices         [N]

    float4* out = (float4*)d_out;

    unsigned n_vec = (unsigned)((long long)in_sizes[0] / 4);   // N*C/4 = 32M
    unsigned per_block = THREADS * UNROLL;                      // 2048
    unsigned blocks = (n_vec + per_block - 1) / per_block;      // 15625

    if (n_vec % per_block == 0) {
        sparse_global_broadcast_kernel<false><<<blocks, THREADS>>>(in, glob, bidx, out, n_vec);
    } else {
        sparse_global_broadcast_kernel<true><<<blocks, THREADS>>>(in, glob, bidx, out, n_vec);
    }
}